// round 1
// baseline (speedup 1.0000x reference)
#include <cuda_runtime.h>
#include <math.h>

#define NN 4096
#define DD 256

// ---------------- scratch (static device globals; no allocation) ----------------
__device__ float  g_h[NN * DD];                 // 4 MB  : h = x*cw + cb
__device__ float4 g_wh1[NN];                    // per-row head logits (src side)
__device__ float4 g_wh2[NN];                    // per-row head logits (dst side)
__device__ float  g_W[NN * NN];                 // 64 MB : combined attention weights
__device__ float  g_max[8];                     // global max of Wh1[0..3], Wh2[0..3]

// ---------------- helpers ----------------
__device__ __forceinline__ void atomicMaxF(float* addr, float v) {
    int old = __float_as_int(*addr);
    while (__int_as_float(old) < v) {
        int assumed = old;
        old = atomicCAS((int*)addr, assumed, __float_as_int(v));
        if (old == assumed) break;
    }
}

__device__ __forceinline__ unsigned long long pk2(float lo, float hi) {
    unsigned long long r;
    asm("mov.b64 %0, {%1, %2};" : "=l"(r) : "f"(lo), "f"(hi));
    return r;
}
__device__ __forceinline__ void upk2(unsigned long long v, float& lo, float& hi) {
    asm("mov.b64 {%0, %1}, %2;" : "=f"(lo), "=f"(hi) : "l"(v));
}
// packed f32x2 FMA: d = a*b + d   (FFMA2, full-rate on sm_103a)
__device__ __forceinline__ void fma2(unsigned long long& d, unsigned long long a,
                                     unsigned long long b) {
    asm("fma.rn.f32x2 %0, %1, %2, %0;" : "+l"(d) : "l"(a), "l"(b));
}

// ---------------- kernel 0: reset global maxima ----------------
__global__ void k0_init() {
    if (threadIdx.x < 8) g_max[threadIdx.x] = -3.4e38f;
}

// ---------------- kernel 1: h = x*cw+cb ; Wh1/Wh2 row dots ; global maxima ----------------
__global__ void k1_prep(const float* __restrict__ x, const float* __restrict__ cw,
                        const float* __restrict__ cb, const float* __restrict__ a) {
    int i = blockIdx.x;
    int d = threadIdx.x;                 // 256 threads == D
    float v = x[i * DD + d] * cw[0] + cb[0];
    g_h[i * DD + d] = v;

    float p[8];
#pragma unroll
    for (int hh = 0; hh < 4; hh++) {
        p[hh]     = v * a[hh * 2 * DD + d];         // a1[hh][d]
        p[4 + hh] = v * a[hh * 2 * DD + DD + d];    // a2[hh][d]
    }
#pragma unroll
    for (int q = 0; q < 8; q++)
#pragma unroll
        for (int o = 16; o > 0; o >>= 1)
            p[q] += __shfl_xor_sync(0xffffffffu, p[q], o);

    __shared__ float red[8][8];
    int w = d >> 5, lane = d & 31;
    if (lane == 0) {
#pragma unroll
        for (int q = 0; q < 8; q++) red[w][q] = p[q];
    }
    __syncthreads();
    if (d < 8) {
        int q = d;
        float s = 0.f;
#pragma unroll
        for (int ww = 0; ww < 8; ww++) s += red[ww][q];
        if (q < 4) ((float*)g_wh1)[i * 4 + q] = s;
        else       ((float*)g_wh2)[i * 4 + (q - 4)] = s;
        atomicMaxF(&g_max[q], s);
    }
}

// ---------------- kernel 2: combined softmax weights W[i,j] = 1/4 * sum_h att_h ----------------
__global__ void __launch_bounds__(256) k2_weights(const int* __restrict__ adj) {
    int i   = blockIdx.x;
    int tid = threadIdx.x;
    int lane = tid & 31, w = tid >> 5;
    __shared__ float red[8][4];
    __shared__ float Sinv[4];

    float4 t1 = g_wh1[i];
    float wh1[4] = {t1.x, t1.y, t1.z, t1.w};
    float M[4];
#pragma unroll
    for (int hh = 0; hh < 4; hh++) M[hh] = g_max[hh] + g_max[4 + hh];  // upper bound on logit
    const int* arow = adj + i * NN;

    // pass A: exp-sum per head (exact softmax: M is a valid global bound)
    float sm[4] = {0.f, 0.f, 0.f, 0.f};
    for (int jb = tid * 4; jb < NN; jb += 1024) {
        int4 av = *(const int4*)(arow + jb);
        int aa[4] = {av.x, av.y, av.z, av.w};
#pragma unroll
        for (int u = 0; u < 4; u++) {
            float4 t2 = g_wh2[jb + u];
            float w2[4] = {t2.x, t2.y, t2.z, t2.w};
#pragma unroll
            for (int hh = 0; hh < 4; hh++) {
                float s = wh1[hh] + w2[hh];
                float e = s > 0.f ? s : expm1f(s);          // ELU
                e = aa[u] > 0 ? e : -9e15f;                  // mask (matches ref constant)
                sm[hh] += expf(e - M[hh]);
            }
        }
    }
#pragma unroll
    for (int hh = 0; hh < 4; hh++)
#pragma unroll
        for (int o = 16; o > 0; o >>= 1)
            sm[hh] += __shfl_xor_sync(0xffffffffu, sm[hh], o);
    if (lane == 0) {
        red[w][0] = sm[0]; red[w][1] = sm[1]; red[w][2] = sm[2]; red[w][3] = sm[3];
    }
    __syncthreads();
    if (tid < 4) {
        float s = 0.f;
#pragma unroll
        for (int ww = 0; ww < 8; ww++) s += red[ww][tid];
        Sinv[tid] = 0.25f / s;
    }
    __syncthreads();
    float inv[4] = {Sinv[0], Sinv[1], Sinv[2], Sinv[3]};

    // pass B: write combined weights
    for (int jb = tid * 4; jb < NN; jb += 1024) {
        int4 av = *(const int4*)(arow + jb);
        int aa[4] = {av.x, av.y, av.z, av.w};
        float res[4];
#pragma unroll
        for (int u = 0; u < 4; u++) {
            float4 t2 = g_wh2[jb + u];
            float w2[4] = {t2.x, t2.y, t2.z, t2.w};
            float acc = 0.f;
#pragma unroll
            for (int hh = 0; hh < 4; hh++) {
                float s = wh1[hh] + w2[hh];
                float e = s > 0.f ? s : expm1f(s);
                e = aa[u] > 0 ? e : -9e15f;
                acc += expf(e - M[hh]) * inv[hh];
            }
            res[u] = acc;
        }
        *(float4*)&g_W[i * NN + jb] = make_float4(res[0], res[1], res[2], res[3]);
    }
}

// ---------------- kernel 3: out = epilogue( W @ h )  (fp32x2 packed SGEMM) ----------------
// tile: 32 rows x 256 cols, BK=32, 128 threads, per-thread 8 rows x 8 cols (4 f32x2 pairs)
__global__ void __launch_bounds__(128) k3_gemm(const float* __restrict__ bias,
                                               float* __restrict__ out) {
    __shared__ float Ws[32][32];
    __shared__ float Hs[32][DD];
    __shared__ float rowsq[32];
    int tid = threadIdx.x;
    int tx = tid & 31, ty = tid >> 5;     // tx: 32 col-groups, ty: 4 row-groups
    int row0 = blockIdx.x * 32;
    if (tid < 32) rowsq[tid] = 0.f;

    unsigned long long acc[8][4];
#pragma unroll
    for (int m = 0; m < 8; m++) {
        acc[m][0] = 0ULL; acc[m][1] = 0ULL; acc[m][2] = 0ULL; acc[m][3] = 0ULL;
    }

    for (int k0 = 0; k0 < NN; k0 += 32) {
        __syncthreads();
        // load W tile: 32x32 floats
#pragma unroll
        for (int it = 0; it < 2; it++) {
            int f = tid + it * 128;
            int r = f >> 3, kq = f & 7;
            *(float4*)&Ws[r][kq * 4] =
                *(const float4*)&g_W[(row0 + r) * NN + k0 + kq * 4];
        }
        // load h tile: 32x256 floats
#pragma unroll
        for (int it = 0; it < 16; it++) {
            int f = tid + it * 128;
            int kk = f >> 6, c4 = f & 63;
            *(float4*)&Hs[kk][c4 * 4] =
                *(const float4*)&g_h[(k0 + kk) * DD + c4 * 4];
        }
        __syncthreads();
#pragma unroll 8
        for (int kk = 0; kk < 32; kk++) {
            float4 ha = *(float4*)&Hs[kk][tx * 4];
            float4 hb = *(float4*)&Hs[kk][128 + tx * 4];
            unsigned long long h0 = pk2(ha.x, ha.y);
            unsigned long long h1 = pk2(ha.z, ha.w);
            unsigned long long h2 = pk2(hb.x, hb.y);
            unsigned long long h3 = pk2(hb.z, hb.w);
#pragma unroll
            for (int m = 0; m < 8; m++) {
                float wv = Ws[ty * 8 + m][kk];
                unsigned long long ww = pk2(wv, wv);
                fma2(acc[m][0], ww, h0);
                fma2(acc[m][1], ww, h1);
                fma2(acc[m][2], ww, h2);
                fma2(acc[m][3], ww, h3);
            }
        }
    }

    // epilogue: o = elu(0.5*hpass + 0.5*h); row L2-normalize; + bias
    float o[8][8];
#pragma unroll
    for (int m = 0; m < 8; m++) {
        int r = row0 + ty * 8 + m;
        float sq = 0.f;
#pragma unroll
        for (int p = 0; p < 4; p++) {
            float lo, hi;
            upk2(acc[m][p], lo, hi);
            int c = (p < 2) ? (tx * 4 + p * 2) : (128 + tx * 4 + (p - 2) * 2);
            float h0v = g_h[r * DD + c];
            float h1v = g_h[r * DD + c + 1];
            float o0 = 0.5f * lo + 0.5f * h0v;
            float o1 = 0.5f * hi + 0.5f * h1v;
            o0 = o0 > 0.f ? o0 : expm1f(o0);
            o1 = o1 > 0.f ? o1 : expm1f(o1);
            o[m][2 * p] = o0; o[m][2 * p + 1] = o1;
            sq += o0 * o0 + o1 * o1;
        }
        atomicAdd(&rowsq[ty * 8 + m], sq);
    }
    __syncthreads();
#pragma unroll
    for (int m = 0; m < 8; m++) {
        int r = row0 + ty * 8 + m;
        float invn = 1.0f / fmaxf(sqrtf(rowsq[ty * 8 + m]), 1e-12f);
        int ca = tx * 4;
        int cb = 128 + tx * 4;
        float4 bva = *(const float4*)&bias[ca];
        float4 bvb = *(const float4*)&bias[cb];
        float4 ra = make_float4(o[m][0] * invn + bva.x, o[m][1] * invn + bva.y,
                                o[m][2] * invn + bva.z, o[m][3] * invn + bva.w);
        float4 rb = make_float4(o[m][4] * invn + bvb.x, o[m][5] * invn + bvb.y,
                                o[m][6] * invn + bvb.z, o[m][7] * invn + bvb.w);
        *(float4*)&out[r * DD + ca] = ra;
        *(float4*)&out[r * DD + cb] = rb;
    }
}

// ---------------- launch ----------------
extern "C" void kernel_launch(void* const* d_in, const int* in_sizes, int n_in,
                              void* d_out, int out_size) {
    const float* x    = (const float*)d_in[0];
    const int*   adj  = (const int*)d_in[1];
    const float* cw   = (const float*)d_in[2];
    const float* cb   = (const float*)d_in[3];
    const float* a    = (const float*)d_in[4];
    const float* bias = (const float*)d_in[5];
    float* out = (float*)d_out;

    k0_init<<<1, 32>>>();
    k1_prep<<<NN, 256>>>(x, cw, cb, a);
    k2_weights<<<NN, 256>>>(adj);
    k3_gemm<<<NN / 32, 128>>>(bias, out);
}

// round 2
// speedup vs baseline: 1.8432x; 1.8432x over previous
#include <cuda_runtime.h>
#include <math.h>

#define NN 4096
#define DD 256

// ---------------- scratch (static device globals; no allocation) ----------------
__device__ float  g_h[NN * DD];                 // 4 MB  : h = x*cw + cb
__device__ float4 g_wh1[NN];                    // per-row head logits (src side)
__device__ float4 g_wh2[NN];                    // per-row head logits (dst side)
__device__ float  g_W[NN * NN];                 // 64 MB : combined attention weights
__device__ float  g_pre[NN * DD];               // 4 MB  : pre-norm epilogue values
__device__ float  g_rowsq[NN];                  // per-row sum of squares
__device__ float  g_max[8];                     // global max of Wh1[0..3], Wh2[0..3]

// ---------------- helpers ----------------
__device__ __forceinline__ void atomicMaxF(float* addr, float v) {
    int old = __float_as_int(*addr);
    while (__int_as_float(old) < v) {
        int assumed = old;
        old = atomicCAS((int*)addr, assumed, __float_as_int(v));
        if (old == assumed) break;
    }
}

__device__ __forceinline__ unsigned long long pk2(float lo, float hi) {
    unsigned long long r;
    asm("mov.b64 %0, {%1, %2};" : "=l"(r) : "f"(lo), "f"(hi));
    return r;
}
__device__ __forceinline__ void upk2(unsigned long long v, float& lo, float& hi) {
    asm("mov.b64 {%0, %1}, %2;" : "=f"(lo), "=f"(hi) : "l"(v));
}
// packed f32x2 FMA: d = a*b + d   (FFMA2, full-rate on sm_103a)
__device__ __forceinline__ void fma2(unsigned long long& d, unsigned long long a,
                                     unsigned long long b) {
    asm("fma.rn.f32x2 %0, %1, %2, %0;" : "+l"(d) : "l"(a), "l"(b));
}

// ---------------- kernel 0: reset global maxima + rowsq ----------------
__global__ void k0_init() {
    int idx = blockIdx.x * blockDim.x + threadIdx.x;
    if (idx < NN) g_rowsq[idx] = 0.f;
    if (idx < 8)  g_max[idx] = -3.4e38f;
}

// ---------------- kernel 1: h = x*cw+cb ; Wh1/Wh2 row dots ; global maxima ----------------
__global__ void k1_prep(const float* __restrict__ x, const float* __restrict__ cw,
                        const float* __restrict__ cb, const float* __restrict__ a) {
    int i = blockIdx.x;
    int d = threadIdx.x;                 // 256 threads == D
    float v = x[i * DD + d] * cw[0] + cb[0];
    g_h[i * DD + d] = v;

    float p[8];
#pragma unroll
    for (int hh = 0; hh < 4; hh++) {
        p[hh]     = v * a[hh * 2 * DD + d];         // a1[hh][d]
        p[4 + hh] = v * a[hh * 2 * DD + DD + d];    // a2[hh][d]
    }
#pragma unroll
    for (int q = 0; q < 8; q++)
#pragma unroll
        for (int o = 16; o > 0; o >>= 1)
            p[q] += __shfl_xor_sync(0xffffffffu, p[q], o);

    __shared__ float red[8][8];
    int w = d >> 5, lane = d & 31;
    if (lane == 0) {
#pragma unroll
        for (int q = 0; q < 8; q++) red[w][q] = p[q];
    }
    __syncthreads();
    if (d < 8) {
        int q = d;
        float s = 0.f;
#pragma unroll
        for (int ww = 0; ww < 8; ww++) s += red[ww][q];
        if (q < 4) ((float*)g_wh1)[i * 4 + q] = s;
        else       ((float*)g_wh2)[i * 4 + (q - 4)] = s;
        atomicMaxF(&g_max[q], s);
    }
}

// ---------------- kernel 2: combined softmax weights W[i,j] = 1/4 * sum_h att_h ----------------
__global__ void __launch_bounds__(256) k2_weights(const int* __restrict__ adj) {
    int i   = blockIdx.x;
    int tid = threadIdx.x;
    int lane = tid & 31, w = tid >> 5;
    __shared__ unsigned char amask[NN];   // 4 KB adjacency cache for pass B
    __shared__ float red[8][4];
    __shared__ float Sinv[4];

    float4 t1 = g_wh1[i];
    float wh1[4] = {t1.x, t1.y, t1.z, t1.w};
    float M[4];
#pragma unroll
    for (int hh = 0; hh < 4; hh++) M[hh] = g_max[hh] + g_max[4 + hh];  // upper bound on logit
    const int* arow = adj + i * NN;

    // pass A: exp-sum per head (exact softmax: M is a valid global bound)
    float sm[4] = {0.f, 0.f, 0.f, 0.f};
    for (int jb = tid * 4; jb < NN; jb += 1024) {
        int4 av = *(const int4*)(arow + jb);
        uchar4 mk = make_uchar4(av.x > 0, av.y > 0, av.z > 0, av.w > 0);
        *(uchar4*)&amask[jb] = mk;
        unsigned char mm[4] = {mk.x, mk.y, mk.z, mk.w};
#pragma unroll
        for (int u = 0; u < 4; u++) {
            float4 t2 = g_wh2[jb + u];
            float w2[4] = {t2.x, t2.y, t2.z, t2.w};
#pragma unroll
            for (int hh = 0; hh < 4; hh++) {
                float s = wh1[hh] + w2[hh];
                float e = s > 0.f ? s : (__expf(s) - 1.f);    // ELU (fast)
                float t = __expf(e - M[hh]);
                sm[hh] += mm[u] ? t : 0.f;
            }
        }
    }
#pragma unroll
    for (int hh = 0; hh < 4; hh++)
#pragma unroll
        for (int o = 16; o > 0; o >>= 1)
            sm[hh] += __shfl_xor_sync(0xffffffffu, sm[hh], o);
    if (lane == 0) {
        red[w][0] = sm[0]; red[w][1] = sm[1]; red[w][2] = sm[2]; red[w][3] = sm[3];
    }
    __syncthreads();
    if (tid < 4) {
        float s = 0.f;
#pragma unroll
        for (int ww = 0; ww < 8; ww++) s += red[ww][tid];
        Sinv[tid] = 0.25f / s;
    }
    __syncthreads();
    float inv[4] = {Sinv[0], Sinv[1], Sinv[2], Sinv[3]};

    // pass B: write combined weights (adj from smem)
    for (int jb = tid * 4; jb < NN; jb += 1024) {
        uchar4 mk = *(uchar4*)&amask[jb];
        unsigned char mm[4] = {mk.x, mk.y, mk.z, mk.w};
        float res[4];
#pragma unroll
        for (int u = 0; u < 4; u++) {
            float4 t2 = g_wh2[jb + u];
            float w2[4] = {t2.x, t2.y, t2.z, t2.w};
            float acc = 0.f;
#pragma unroll
            for (int hh = 0; hh < 4; hh++) {
                float s = wh1[hh] + w2[hh];
                float e = s > 0.f ? s : (__expf(s) - 1.f);
                float t = __expf(e - M[hh]) * inv[hh];
                acc += mm[u] ? t : 0.f;
            }
            res[u] = acc;
        }
        *(float4*)&g_W[i * NN + jb] = make_float4(res[0], res[1], res[2], res[3]);
    }
}

// ---------------- kernel 3: pre = elu(0.5*(W@h) + 0.5*h), rowsq accumulation ----------------
// tile: 32 rows x 128 cols, BK=32, 128 threads, per-thread 8 rows x 4 cols (2 f32x2 pairs)
// grid: (4096/32, 256/128) = (128, 2) = 256 blocks -> ~2 CTAs/SM
__global__ void __launch_bounds__(128) k3_gemm() {
    __shared__ float Ws[32][32];
    __shared__ float Hs[32][128];
    int tid = threadIdx.x;
    int tx = tid & 31, ty = tid >> 5;     // tx: 32 col-groups of 4, ty: 4 row-groups of 8
    int row0 = blockIdx.x * 32;
    int col0 = blockIdx.y * 128;

    unsigned long long acc[8][2];
#pragma unroll
    for (int m = 0; m < 8; m++) { acc[m][0] = 0ULL; acc[m][1] = 0ULL; }

    // prefetch registers
    float4 wreg[2], hreg[8];
    {
        const int k0 = 0;
#pragma unroll
        for (int it = 0; it < 2; it++) {
            int f = tid + it * 128, r = f >> 3, kq = f & 7;
            wreg[it] = *(const float4*)&g_W[(row0 + r) * NN + k0 + kq * 4];
        }
#pragma unroll
        for (int it = 0; it < 8; it++) {
            int f = tid + it * 128, kk = f >> 5, c4 = f & 31;
            hreg[it] = *(const float4*)&g_h[(k0 + kk) * DD + col0 + c4 * 4];
        }
    }

    for (int k0 = 0; k0 < NN; k0 += 32) {
        __syncthreads();
#pragma unroll
        for (int it = 0; it < 2; it++) {
            int f = tid + it * 128, r = f >> 3, kq = f & 7;
            *(float4*)&Ws[r][kq * 4] = wreg[it];
        }
#pragma unroll
        for (int it = 0; it < 8; it++) {
            int f = tid + it * 128, kk = f >> 5, c4 = f & 31;
            *(float4*)&Hs[kk][c4 * 4] = hreg[it];
        }
        __syncthreads();

        int kn = k0 + 32;
        if (kn < NN) {
#pragma unroll
            for (int it = 0; it < 2; it++) {
                int f = tid + it * 128, r = f >> 3, kq = f & 7;
                wreg[it] = *(const float4*)&g_W[(row0 + r) * NN + kn + kq * 4];
            }
#pragma unroll
            for (int it = 0; it < 8; it++) {
                int f = tid + it * 128, kk = f >> 5, c4 = f & 31;
                hreg[it] = *(const float4*)&g_h[(kn + kk) * DD + col0 + c4 * 4];
            }
        }

#pragma unroll 8
        for (int kk = 0; kk < 32; kk++) {
            unsigned long long h0 = *(unsigned long long*)&Hs[kk][tx * 4];
            unsigned long long h1 = *(unsigned long long*)&Hs[kk][tx * 4 + 2];
#pragma unroll
            for (int m = 0; m < 8; m++) {
                float wv = Ws[ty * 8 + m][kk];
                unsigned long long ww = pk2(wv, wv);
                fma2(acc[m][0], ww, h0);
                fma2(acc[m][1], ww, h1);
            }
        }
    }

    // epilogue: o = elu(0.5*hpass + 0.5*h); partial rowsq via warp-reduce + atomic
#pragma unroll
    for (int m = 0; m < 8; m++) {
        int r = row0 + ty * 8 + m;
        int c = col0 + tx * 4;
        float4 hv = *(const float4*)&g_h[r * DD + c];
        float lo0, hi0, lo1, hi1;
        upk2(acc[m][0], lo0, hi0);
        upk2(acc[m][1], lo1, hi1);
        float o0 = 0.5f * (lo0 + hv.x);
        float o1 = 0.5f * (hi0 + hv.y);
        float o2 = 0.5f * (lo1 + hv.z);
        float o3 = 0.5f * (hi1 + hv.w);
        o0 = o0 > 0.f ? o0 : (__expf(o0) - 1.f);
        o1 = o1 > 0.f ? o1 : (__expf(o1) - 1.f);
        o2 = o2 > 0.f ? o2 : (__expf(o2) - 1.f);
        o3 = o3 > 0.f ? o3 : (__expf(o3) - 1.f);
        *(float4*)&g_pre[r * DD + c] = make_float4(o0, o1, o2, o3);
        float sq = o0 * o0 + o1 * o1 + o2 * o2 + o3 * o3;
#pragma unroll
        for (int o = 16; o > 0; o >>= 1)
            sq += __shfl_xor_sync(0xffffffffu, sq, o);
        if (tx == 0) atomicAdd(&g_rowsq[r], sq);
    }
}

// ---------------- kernel 4: normalize + bias ----------------
__global__ void __launch_bounds__(256) k4_norm(const float* __restrict__ bias,
                                               float* __restrict__ out) {
    int r = blockIdx.x;
    int c = threadIdx.x;
    float invn = 1.0f / fmaxf(sqrtf(g_rowsq[r]), 1e-12f);
    out[r * DD + c] = g_pre[r * DD + c] * invn + bias[c];
}

// ---------------- launch ----------------
extern "C" void kernel_launch(void* const* d_in, const int* in_sizes, int n_in,
                              void* d_out, int out_size) {
    const float* x    = (const float*)d_in[0];
    const int*   adj  = (const int*)d_in[1];
    const float* cw   = (const float*)d_in[2];
    const float* cb   = (const float*)d_in[3];
    const float* a    = (const float*)d_in[4];
    const float* bias = (const float*)d_in[5];
    float* out = (float*)d_out;

    k0_init<<<16, 256>>>();
    k1_prep<<<NN, 256>>>(x, cw, cb, a);
    k2_weights<<<NN, 256>>>(adj);
    dim3 g3(NN / 32, 2);
    k3_gemm<<<g3, 128>>>();
    k4_norm<<<NN, 256>>>(bias, out);
}

// round 5
// speedup vs baseline: 3.5601x; 1.9315x over previous
#include <cuda_runtime.h>
#include <cuda_bf16.h>
#include <math.h>
#include <stdint.h>

#define NN 4096
#define DD 256

// ---------------- scratch (static device globals; no allocation) ----------------
__device__ float          g_h[NN * DD];          // 4 MB : h fp32 (epilogue + logits)
__device__ __nv_bfloat16  g_hb[NN * DD];         // 2 MB : h bf16 [j][d] (B operand)
__device__ __nv_bfloat16  g_Wb[(size_t)NN * NN]; // 32 MB: combined attention weights bf16
__device__ float4 g_wh1[NN];
__device__ float4 g_wh2[NN];
__device__ float  g_pre[NN * DD];                // pre-norm epilogue values
__device__ float  g_rowsq[NN];
__device__ float  g_max[8];

// ---------------- helpers ----------------
__device__ __forceinline__ void atomicMaxF(float* addr, float v) {
    int old = __float_as_int(*addr);
    while (__int_as_float(old) < v) {
        int assumed = old;
        old = atomicCAS((int*)addr, assumed, __float_as_int(v));
        if (old == assumed) break;
    }
}
__device__ __forceinline__ uint32_t smem_u32(const void* p) {
    uint32_t a;
    asm("{ .reg .u64 t; cvta.to.shared.u64 t, %1; cvt.u32.u64 %0, t; }" : "=r"(a) : "l"(p));
    return a;
}
__device__ __forceinline__ void ldmA(uint32_t* r, uint32_t addr) {
    asm volatile("ldmatrix.sync.aligned.m8n8.x4.shared.b16 {%0,%1,%2,%3}, [%4];"
                 : "=r"(r[0]), "=r"(r[1]), "=r"(r[2]), "=r"(r[3]) : "r"(addr));
}
__device__ __forceinline__ void ldmBT(uint32_t* r, uint32_t addr) {
    asm volatile("ldmatrix.sync.aligned.m8n8.x4.trans.shared.b16 {%0,%1,%2,%3}, [%4];"
                 : "=r"(r[0]), "=r"(r[1]), "=r"(r[2]), "=r"(r[3]) : "r"(addr));
}
__device__ __forceinline__ void mma16816(float* c, const uint32_t* a, uint32_t b0, uint32_t b1) {
    asm volatile("mma.sync.aligned.m16n8k16.row.col.f32.bf16.bf16.f32 "
                 "{%0,%1,%2,%3}, {%4,%5,%6,%7}, {%8,%9}, {%0,%1,%2,%3};"
                 : "+f"(c[0]), "+f"(c[1]), "+f"(c[2]), "+f"(c[3])
                 : "r"(a[0]), "r"(a[1]), "r"(a[2]), "r"(a[3]), "r"(b0), "r"(b1));
}

// ---------------- kernel 0: reset maxima + rowsq ----------------
__global__ void k0_init() {
    int idx = blockIdx.x * blockDim.x + threadIdx.x;
    if (idx < NN) g_rowsq[idx] = 0.f;
    if (idx < 8)  g_max[idx] = -3.4e38f;
}

// ---------------- kernel 1: h, h(bf16), Wh1/Wh2, maxima ----------------
__global__ void k1_prep(const float* __restrict__ x, const float* __restrict__ cw,
                        const float* __restrict__ cb, const float* __restrict__ a) {
    int i = blockIdx.x;
    int d = threadIdx.x;
    float v = x[i * DD + d] * cw[0] + cb[0];
    g_h[i * DD + d] = v;
    g_hb[i * DD + d] = __float2bfloat16_rn(v);

    float p[8];
#pragma unroll
    for (int hh = 0; hh < 4; hh++) {
        p[hh]     = v * a[hh * 2 * DD + d];
        p[4 + hh] = v * a[hh * 2 * DD + DD + d];
    }
#pragma unroll
    for (int q = 0; q < 8; q++)
#pragma unroll
        for (int o = 16; o > 0; o >>= 1)
            p[q] += __shfl_xor_sync(0xffffffffu, p[q], o);

    __shared__ float red[8][8];
    int w = d >> 5, lane = d & 31;
    if (lane == 0) {
#pragma unroll
        for (int q = 0; q < 8; q++) red[w][q] = p[q];
    }
    __syncthreads();
    if (d < 8) {
        int q = d;
        float s = 0.f;
#pragma unroll
        for (int ww = 0; ww < 8; ww++) s += red[ww][q];
        if (q < 4) ((float*)g_wh1)[i * 4 + q] = s;
        else       ((float*)g_wh2)[i * 4 + (q - 4)] = s;
        atomicMaxF(&g_max[q], s);
    }
}

// ---------------- kernel 2: W[i,j] = 1/4 sum_h softmax (bf16 out, exp cached) ----------------
__global__ void __launch_bounds__(256) k2_weights(const int* __restrict__ adj) {
    int i   = blockIdx.x;
    int tid = threadIdx.x;
    int lane = tid & 31, w = tid >> 5;
    __shared__ float red[8][4];
    __shared__ float Sinv[4];

    float4 t1 = g_wh1[i];
    float wh1[4] = {t1.x, t1.y, t1.z, t1.w};
    float M[4];
#pragma unroll
    for (int hh = 0; hh < 4; hh++) M[hh] = g_max[hh] + g_max[4 + hh];
    const int* arow = adj + i * NN;

    // pass A: compute all masked exp terms once, cache in registers
    float tc[4][16];
    float sm[4] = {0.f, 0.f, 0.f, 0.f};
#pragma unroll
    for (int it = 0; it < 4; it++) {
        int jb = tid * 4 + it * 1024;
        int4 av = *(const int4*)(arow + jb);
        int aa[4] = {av.x, av.y, av.z, av.w};
#pragma unroll
        for (int u = 0; u < 4; u++) {
            float4 t2 = g_wh2[jb + u];
            float w2[4] = {t2.x, t2.y, t2.z, t2.w};
#pragma unroll
            for (int hh = 0; hh < 4; hh++) {
                float s = wh1[hh] + w2[hh];
                float e = s > 0.f ? s : (__expf(s) - 1.f);
                float t = aa[u] > 0 ? __expf(e - M[hh]) : 0.f;
                tc[hh][it * 4 + u] = t;
                sm[hh] += t;
            }
        }
    }
#pragma unroll
    for (int hh = 0; hh < 4; hh++)
#pragma unroll
        for (int o = 16; o > 0; o >>= 1)
            sm[hh] += __shfl_xor_sync(0xffffffffu, sm[hh], o);
    if (lane == 0) {
        red[w][0] = sm[0]; red[w][1] = sm[1]; red[w][2] = sm[2]; red[w][3] = sm[3];
    }
    __syncthreads();
    if (tid < 4) {
        float s = 0.f;
#pragma unroll
        for (int ww = 0; ww < 8; ww++) s += red[ww][tid];
        Sinv[tid] = 0.25f / s;
    }
    __syncthreads();
    float inv[4] = {Sinv[0], Sinv[1], Sinv[2], Sinv[3]};

    // pass B: combine cached terms, write bf16
#pragma unroll
    for (int it = 0; it < 4; it++) {
        int jb = tid * 4 + it * 1024;
        float res[4];
#pragma unroll
        for (int u = 0; u < 4; u++) {
            int li = it * 4 + u;
            res[u] = tc[0][li] * inv[0] + tc[1][li] * inv[1] +
                     tc[2][li] * inv[2] + tc[3][li] * inv[3];
        }
        __nv_bfloat162 r0 = __floats2bfloat162_rn(res[0], res[1]);
        __nv_bfloat162 r1 = __floats2bfloat162_rn(res[2], res[3]);
        uint2 pk = make_uint2(*(uint32_t*)&r0, *(uint32_t*)&r1);
        *(uint2*)&g_Wb[(size_t)i * NN + jb] = pk;
    }
}

// ---------------- kernel 3: bf16 mma.sync GEMM + fused epilogue ----------------
// BM=128, BN=64, BK=32; 128 threads (4 warps), warp w: rows w*32..w*32+31, all 64 cols.
// Per warp: 2 (m16) x 8 (n8) mma tiles. grid (32, 4) = 128 CTAs.
#define BK 32
#define A_STRIDE 40   // bf16 elems per row (32 + 8 pad) -> 80B
#define B_STRIDE 72   // bf16 elems per row (64 + 8 pad) -> 144B

__global__ void __launch_bounds__(128) k3_gemm() {
    __shared__ __nv_bfloat16 As[2][128][A_STRIDE];
    __shared__ __nv_bfloat16 Bs[2][BK][B_STRIDE];
    int tid = threadIdx.x;
    int w = tid >> 5, lane = tid & 31;
    int row0 = blockIdx.x * 128;
    int col0 = blockIdx.y * 64;

    float acc[2][8][4];
#pragma unroll
    for (int mt = 0; mt < 2; mt++)
#pragma unroll
        for (int nt = 0; nt < 8; nt++)
#pragma unroll
            for (int q = 0; q < 4; q++) acc[mt][nt][q] = 0.f;

    // per-thread load coords: B tile 32 rows x 64 cols = 256 uint4 -> 2 per thread
    int brow = tid >> 2, bq = tid & 3;

    uint4 aPf[4], bPf[2];
    {
#pragma unroll
        for (int it = 0; it < 4; it++) {
            int idx = tid + it * 128;
            int r = idx >> 2, q = idx & 3;
            aPf[it] = *(const uint4*)&g_Wb[(size_t)(row0 + r) * NN + q * 8];
        }
#pragma unroll
        for (int u = 0; u < 2; u++)
            bPf[u] = *(const uint4*)&g_hb[(size_t)brow * DD + col0 + u * 32 + bq * 8];
    }

    const int NK = NN / BK;   // 128
    for (int t = 0; t < NK; t++) {
        int buf = t & 1;
        __syncthreads();
#pragma unroll
        for (int it = 0; it < 4; it++) {
            int idx = tid + it * 128;
            int r = idx >> 2, q = idx & 3;
            *(uint4*)&As[buf][r][q * 8] = aPf[it];
        }
#pragma unroll
        for (int u = 0; u < 2; u++)
            *(uint4*)&Bs[buf][brow][u * 32 + bq * 8] = bPf[u];
        __syncthreads();

        if (t + 1 < NK) {
            int kn = (t + 1) * BK;
#pragma unroll
            for (int it = 0; it < 4; it++) {
                int idx = tid + it * 128;
                int r = idx >> 2, q = idx & 3;
                aPf[it] = *(const uint4*)&g_Wb[(size_t)(row0 + r) * NN + kn + q * 8];
            }
#pragma unroll
            for (int u = 0; u < 2; u++)
                bPf[u] = *(const uint4*)&g_hb[(size_t)(kn + brow) * DD + col0 + u * 32 + bq * 8];
        }

#pragma unroll
        for (int ks = 0; ks < 2; ks++) {
            uint32_t a[2][4];
#pragma unroll
            for (int mt = 0; mt < 2; mt++) {
                uint32_t addr = smem_u32(
                    &As[buf][w * 32 + mt * 16 + (lane & 15)][ks * 16 + (lane >> 4) * 8]);
                ldmA(a[mt], addr);
            }
            uint32_t b[4][4];
#pragma unroll
            for (int nt2 = 0; nt2 < 4; nt2++) {
                uint32_t addr = smem_u32(
                    &Bs[buf][ks * 16 + (lane & 15)][nt2 * 16 + (lane >> 4) * 8]);
                ldmBT(b[nt2], addr);
            }
#pragma unroll
            for (int mt = 0; mt < 2; mt++)
#pragma unroll
                for (int nt = 0; nt < 8; nt++)
                    mma16816(acc[mt][nt], a[mt],
                             b[nt >> 1][(nt & 1) * 2], b[nt >> 1][(nt & 1) * 2 + 1]);
        }
    }

    // epilogue: o = elu(0.5*hpass + 0.5*h); rowsq via quad-reduce + atomic; pre-norm store
#pragma unroll
    for (int mt = 0; mt < 2; mt++) {
        int rT = row0 + w * 32 + mt * 16 + (lane >> 2);
        int rB = rT + 8;
        float sqT = 0.f, sqB = 0.f;
#pragma unroll
        for (int nt = 0; nt < 8; nt++) {
            int c = col0 + nt * 8 + (lane & 3) * 2;
            float2 hT = *(const float2*)&g_h[rT * DD + c];
            float2 hB = *(const float2*)&g_h[rB * DD + c];
            float o0 = 0.5f * (acc[mt][nt][0] + hT.x);
            float o1 = 0.5f * (acc[mt][nt][1] + hT.y);
            float o2 = 0.5f * (acc[mt][nt][2] + hB.x);
            float o3 = 0.5f * (acc[mt][nt][3] + hB.y);
            o0 = o0 > 0.f ? o0 : (__expf(o0) - 1.f);
            o1 = o1 > 0.f ? o1 : (__expf(o1) - 1.f);
            o2 = o2 > 0.f ? o2 : (__expf(o2) - 1.f);
            o3 = o3 > 0.f ? o3 : (__expf(o3) - 1.f);
            *(float2*)&g_pre[rT * DD + c] = make_float2(o0, o1);
            *(float2*)&g_pre[rB * DD + c] = make_float2(o2, o3);
            sqT += o0 * o0 + o1 * o1;
            sqB += o2 * o2 + o3 * o3;
        }
        // reduce across the 4 lanes sharing each row
        sqT += __shfl_xor_sync(0xffffffffu, sqT, 1);
        sqT += __shfl_xor_sync(0xffffffffu, sqT, 2);
        sqB += __shfl_xor_sync(0xffffffffu, sqB, 1);
        sqB += __shfl_xor_sync(0xffffffffu, sqB, 2);
        if ((lane & 3) == 0) {
            atomicAdd(&g_rowsq[rT], sqT);
            atomicAdd(&g_rowsq[rB], sqB);
        }
    }
}

// ---------------- kernel 4: normalize + bias ----------------
__global__ void __launch_bounds__(256) k4_norm(const float* __restrict__ bias,
                                               float* __restrict__ out) {
    int r = blockIdx.x;
    int c = threadIdx.x;
    float invn = 1.0f / fmaxf(sqrtf(g_rowsq[r]), 1e-12f);
    out[r * DD + c] = g_pre[r * DD + c] * invn + bias[c];
}

// ---------------- launch ----------------
extern "C" void kernel_launch(void* const* d_in, const int* in_sizes, int n_in,
                              void* d_out, int out_size) {
    const float* x    = (const float*)d_in[0];
    const int*   adj  = (const int*)d_in[1];
    const float* cw   = (const float*)d_in[2];
    const float* cb   = (const float*)d_in[3];
    const float* a    = (const float*)d_in[4];
    const float* bias = (const float*)d_in[5];
    float* out = (float*)d_out;

    k0_init<<<16, 256>>>();
    k1_prep<<<NN, 256>>>(x, cw, cb, a);
    k2_weights<<<NN, 256>>>(adj);
    dim3 g3(NN / 128, DD / 64);
    k3_gemm<<<g3, 128>>>();
    k4_norm<<<NN, 256>>>(bias, out);
}

// round 6
// speedup vs baseline: 4.6504x; 1.3063x over previous
#include <cuda_runtime.h>
#include <cuda_bf16.h>
#include <math.h>
#include <stdint.h>

#define NN 4096
#define DD 256

// ---------------- scratch (static device globals; no allocation) ----------------
__device__ float          g_h[NN * DD];          // 4 MB : h fp32 (epilogue + logits)
__device__ __nv_bfloat16  g_hb[NN * DD];         // 2 MB : h bf16 [j][d] (B operand)
__device__ __nv_bfloat16  g_Wb[(size_t)NN * NN]; // 32 MB: combined attention weights bf16
__device__ float4 g_wh1[NN];
__device__ float4 g_wh2[NN];
__device__ float  g_pre[NN * DD];                // pre-norm epilogue values
__device__ float  g_rowsq[NN];
__device__ float  g_max[8];

// ---------------- helpers ----------------
__device__ __forceinline__ void atomicMaxF(float* addr, float v) {
    int old = __float_as_int(*addr);
    while (__int_as_float(old) < v) {
        int assumed = old;
        old = atomicCAS((int*)addr, assumed, __float_as_int(v));
        if (old == assumed) break;
    }
}
__device__ __forceinline__ uint32_t smem_u32(const void* p) {
    uint32_t a;
    asm("{ .reg .u64 t; cvta.to.shared.u64 t, %1; cvt.u32.u64 %0, t; }" : "=r"(a) : "l"(p));
    return a;
}
__device__ __forceinline__ void cpasync16(uint32_t dst, const void* src) {
    asm volatile("cp.async.cg.shared.global [%0], [%1], 16;" :: "r"(dst), "l"(src));
}
#define CP_COMMIT()  asm volatile("cp.async.commit_group;" ::: "memory")
#define CP_WAIT(n)   asm volatile("cp.async.wait_group %0;" :: "n"(n) : "memory")
__device__ __forceinline__ void ldmA(uint32_t* r, uint32_t addr) {
    asm volatile("ldmatrix.sync.aligned.m8n8.x4.shared.b16 {%0,%1,%2,%3}, [%4];"
                 : "=r"(r[0]), "=r"(r[1]), "=r"(r[2]), "=r"(r[3]) : "r"(addr));
}
__device__ __forceinline__ void ldmBT(uint32_t* r, uint32_t addr) {
    asm volatile("ldmatrix.sync.aligned.m8n8.x4.trans.shared.b16 {%0,%1,%2,%3}, [%4];"
                 : "=r"(r[0]), "=r"(r[1]), "=r"(r[2]), "=r"(r[3]) : "r"(addr));
}
__device__ __forceinline__ void mma16816(float* c, const uint32_t* a, uint32_t b0, uint32_t b1) {
    asm volatile("mma.sync.aligned.m16n8k16.row.col.f32.bf16.bf16.f32 "
                 "{%0,%1,%2,%3}, {%4,%5,%6,%7}, {%8,%9}, {%0,%1,%2,%3};"
                 : "+f"(c[0]), "+f"(c[1]), "+f"(c[2]), "+f"(c[3])
                 : "r"(a[0]), "r"(a[1]), "r"(a[2]), "r"(a[3]), "r"(b0), "r"(b1));
}

// ---------------- kernel 0: reset maxima + rowsq ----------------
__global__ void k0_init() {
    int idx = blockIdx.x * blockDim.x + threadIdx.x;
    if (idx < NN) g_rowsq[idx] = 0.f;
    if (idx < 8)  g_max[idx] = -3.4e38f;
}

// ---------------- kernel 1: h, h(bf16), Wh1/Wh2, maxima ----------------
__global__ void k1_prep(const float* __restrict__ x, const float* __restrict__ cw,
                        const float* __restrict__ cb, const float* __restrict__ a) {
    int i = blockIdx.x;
    int d = threadIdx.x;
    float v = x[i * DD + d] * cw[0] + cb[0];
    g_h[i * DD + d] = v;
    g_hb[i * DD + d] = __float2bfloat16_rn(v);

    float p[8];
#pragma unroll
    for (int hh = 0; hh < 4; hh++) {
        p[hh]     = v * a[hh * 2 * DD + d];
        p[4 + hh] = v * a[hh * 2 * DD + DD + d];
    }
#pragma unroll
    for (int q = 0; q < 8; q++)
#pragma unroll
        for (int o = 16; o > 0; o >>= 1)
            p[q] += __shfl_xor_sync(0xffffffffu, p[q], o);

    __shared__ float red[8][8];
    int w = d >> 5, lane = d & 31;
    if (lane == 0) {
#pragma unroll
        for (int q = 0; q < 8; q++) red[w][q] = p[q];
    }
    __syncthreads();
    if (d < 8) {
        int q = d;
        float s = 0.f;
#pragma unroll
        for (int ww = 0; ww < 8; ww++) s += red[ww][q];
        if (q < 4) ((float*)g_wh1)[i * 4 + q] = s;
        else       ((float*)g_wh2)[i * 4 + (q - 4)] = s;
        atomicMaxF(&g_max[q], s);
    }
}

// ---------------- kernel 2: W[i,j] = 1/4 sum_h softmax (bf16 out, exp cached) ----------------
__global__ void __launch_bounds__(256) k2_weights(const int* __restrict__ adj) {
    int i   = blockIdx.x;
    int tid = threadIdx.x;
    int lane = tid & 31, w = tid >> 5;
    __shared__ float red[8][4];
    __shared__ float Sinv[4];

    float4 t1 = g_wh1[i];
    float wh1[4] = {t1.x, t1.y, t1.z, t1.w};
    float M[4];
#pragma unroll
    for (int hh = 0; hh < 4; hh++) M[hh] = g_max[hh] + g_max[4 + hh];
    const int* arow = adj + i * NN;

    // pass A: compute all masked exp terms once, cache in registers
    float tc[4][16];
    float sm[4] = {0.f, 0.f, 0.f, 0.f};
#pragma unroll
    for (int it = 0; it < 4; it++) {
        int jb = tid * 4 + it * 1024;
        int4 av = *(const int4*)(arow + jb);
        int aa[4] = {av.x, av.y, av.z, av.w};
#pragma unroll
        for (int u = 0; u < 4; u++) {
            float4 t2 = g_wh2[jb + u];
            float w2[4] = {t2.x, t2.y, t2.z, t2.w};
#pragma unroll
            for (int hh = 0; hh < 4; hh++) {
                float s = wh1[hh] + w2[hh];
                float e = s > 0.f ? s : (__expf(s) - 1.f);
                float t = aa[u] > 0 ? __expf(e - M[hh]) : 0.f;
                tc[hh][it * 4 + u] = t;
                sm[hh] += t;
            }
        }
    }
#pragma unroll
    for (int hh = 0; hh < 4; hh++)
#pragma unroll
        for (int o = 16; o > 0; o >>= 1)
            sm[hh] += __shfl_xor_sync(0xffffffffu, sm[hh], o);
    if (lane == 0) {
        red[w][0] = sm[0]; red[w][1] = sm[1]; red[w][2] = sm[2]; red[w][3] = sm[3];
    }
    __syncthreads();
    if (tid < 4) {
        float s = 0.f;
#pragma unroll
        for (int ww = 0; ww < 8; ww++) s += red[ww][tid];
        Sinv[tid] = 0.25f / s;
    }
    __syncthreads();
    float inv[4] = {Sinv[0], Sinv[1], Sinv[2], Sinv[3]};

    // pass B: combine cached terms, write bf16
#pragma unroll
    for (int it = 0; it < 4; it++) {
        int jb = tid * 4 + it * 1024;
        float res[4];
#pragma unroll
        for (int u = 0; u < 4; u++) {
            int li = it * 4 + u;
            res[u] = tc[0][li] * inv[0] + tc[1][li] * inv[1] +
                     tc[2][li] * inv[2] + tc[3][li] * inv[3];
        }
        __nv_bfloat162 r0 = __floats2bfloat162_rn(res[0], res[1]);
        __nv_bfloat162 r1 = __floats2bfloat162_rn(res[2], res[3]);
        uint2 pk = make_uint2(*(uint32_t*)&r0, *(uint32_t*)&r1);
        *(uint2*)&g_Wb[(size_t)i * NN + jb] = pk;
    }
}

// ---------------- kernel 3: bf16 mma.sync GEMM, cp.async 3-stage pipeline ----------------
// BM=64, BN=64, BK=32; 128 threads (4 warps), warp w: rows w*16..w*16+15, all 64 cols.
// grid (64, 4) = 256 CTAs.
#define BK 32
#define NSTAGE 3
#define A_STRIDE 40   // bf16 elems per row (32 + 8 pad) -> 80B (16B-aligned rows)
#define B_STRIDE 72   // bf16 elems per row (64 + 8 pad) -> 144B (16B-aligned rows)

__global__ void __launch_bounds__(128) k3_gemm() {
    __shared__ __nv_bfloat16 As[NSTAGE][64][A_STRIDE];
    __shared__ __nv_bfloat16 Bs[NSTAGE][BK][B_STRIDE];
    int tid = threadIdx.x;
    int w = tid >> 5, lane = tid & 31;
    int row0 = blockIdx.x * 64;
    int col0 = blockIdx.y * 64;

    float acc[8][4];
#pragma unroll
    for (int nt = 0; nt < 8; nt++)
#pragma unroll
        for (int q = 0; q < 4; q++) acc[nt][q] = 0.f;

    // A slab: 64 rows x 32 cols = 256 uint4 -> 2 per thread
    int ar0 = tid >> 2,  aq0 = tid & 3;
    int ar1 = (tid + 128) >> 2, aq1 = (tid + 128) & 3;
    // B slab: 32 rows x 64 cols = 256 uint4 -> 2 per thread
    int br0 = tid >> 3,  bq0 = tid & 7;
    int br1 = (tid + 128) >> 3, bq1 = (tid + 128) & 7;

    uint32_t sA[NSTAGE][2], sB[NSTAGE][2];
#pragma unroll
    for (int s = 0; s < NSTAGE; s++) {
        sA[s][0] = smem_u32(&As[s][ar0][aq0 * 8]);
        sA[s][1] = smem_u32(&As[s][ar1][aq1 * 8]);
        sB[s][0] = smem_u32(&Bs[s][br0][bq0 * 8]);
        sB[s][1] = smem_u32(&Bs[s][br1][bq1 * 8]);
    }

    const int NK = NN / BK;   // 128

#define LOAD_TILE(s, t)                                                          \
    do {                                                                         \
        int k0_ = (t) * BK;                                                      \
        cpasync16(sA[s][0], &g_Wb[(size_t)(row0 + ar0) * NN + k0_ + aq0 * 8]);   \
        cpasync16(sA[s][1], &g_Wb[(size_t)(row0 + ar1) * NN + k0_ + aq1 * 8]);   \
        cpasync16(sB[s][0], &g_hb[(size_t)(k0_ + br0) * DD + col0 + bq0 * 8]);   \
        cpasync16(sB[s][1], &g_hb[(size_t)(k0_ + br1) * DD + col0 + bq1 * 8]);   \
    } while (0)

    LOAD_TILE(0, 0); CP_COMMIT();
    LOAD_TILE(1, 1); CP_COMMIT();

    for (int t = 0; t < NK; t++) {
        int nxt = t + NSTAGE - 1;
        if (nxt < NK) LOAD_TILE(nxt % NSTAGE, nxt);
        CP_COMMIT();
        CP_WAIT(NSTAGE - 1);      // tile t's group complete
        __syncthreads();

        int buf = t % NSTAGE;
#pragma unroll
        for (int ks = 0; ks < 2; ks++) {
            uint32_t a[4];
            ldmA(a, smem_u32(&As[buf][w * 16 + (lane & 15)][ks * 16 + (lane >> 4) * 8]));
            uint32_t b[4][4];
#pragma unroll
            for (int nt2 = 0; nt2 < 4; nt2++)
                ldmBT(b[nt2], smem_u32(&Bs[buf][ks * 16 + (lane & 15)][nt2 * 16 + (lane >> 4) * 8]));
#pragma unroll
            for (int nt = 0; nt < 8; nt++)
                mma16816(acc[nt], a, b[nt >> 1][(nt & 1) * 2], b[nt >> 1][(nt & 1) * 2 + 1]);
        }
        __syncthreads();
    }
#undef LOAD_TILE

    // epilogue: o = elu(0.5*hpass + 0.5*h); rowsq via quad-reduce + atomic; pre-norm store
    int rT = row0 + w * 16 + (lane >> 2);
    int rB = rT + 8;
    float sqT = 0.f, sqB = 0.f;
#pragma unroll
    for (int nt = 0; nt < 8; nt++) {
        int c = col0 + nt * 8 + (lane & 3) * 2;
        float2 hT = *(const float2*)&g_h[rT * DD + c];
        float2 hB = *(const float2*)&g_h[rB * DD + c];
        float o0 = 0.5f * (acc[nt][0] + hT.x);
        float o1 = 0.5f * (acc[nt][1] + hT.y);
        float o2 = 0.5f * (acc[nt][2] + hB.x);
        float o3 = 0.5f * (acc[nt][3] + hB.y);
        o0 = o0 > 0.f ? o0 : (__expf(o0) - 1.f);
        o1 = o1 > 0.f ? o1 : (__expf(o1) - 1.f);
        o2 = o2 > 0.f ? o2 : (__expf(o2) - 1.f);
        o3 = o3 > 0.f ? o3 : (__expf(o3) - 1.f);
        *(float2*)&g_pre[rT * DD + c] = make_float2(o0, o1);
        *(float2*)&g_pre[rB * DD + c] = make_float2(o2, o3);
        sqT += o0 * o0 + o1 * o1;
        sqB += o2 * o2 + o3 * o3;
    }
    sqT += __shfl_xor_sync(0xffffffffu, sqT, 1);
    sqT += __shfl_xor_sync(0xffffffffu, sqT, 2);
    sqB += __shfl_xor_sync(0xffffffffu, sqB, 1);
    sqB += __shfl_xor_sync(0xffffffffu, sqB, 2);
    if ((lane & 3) == 0) {
        atomicAdd(&g_rowsq[rT], sqT);
        atomicAdd(&g_rowsq[rB], sqB);
    }
}

// ---------------- kernel 4: normalize + bias ----------------
__global__ void __launch_bounds__(256) k4_norm(const float* __restrict__ bias,
                                               float* __restrict__ out) {
    int r = blockIdx.x;
    int c = threadIdx.x;
    float invn = 1.0f / fmaxf(sqrtf(g_rowsq[r]), 1e-12f);
    out[r * DD + c] = g_pre[r * DD + c] * invn + bias[c];
}

// ---------------- launch ----------------
extern "C" void kernel_launch(void* const* d_in, const int* in_sizes, int n_in,
                              void* d_out, int out_size) {
    const float* x    = (const float*)d_in[0];
    const int*   adj  = (const int*)d_in[1];
    const float* cw   = (const float*)d_in[2];
    const float* cb   = (const float*)d_in[3];
    const float* a    = (const float*)d_in[4];
    const float* bias = (const float*)d_in[5];
    float* out = (float*)d_out;

    k0_init<<<16, 256>>>();
    k1_prep<<<NN, 256>>>(x, cw, cb, a);
    k2_weights<<<NN, 256>>>(adj);
    dim3 g3(NN / 64, DD / 64);
    k3_gemm<<<g3, 128>>>();
    k4_norm<<<NN, 256>>>(bias, out);
}

// round 7
// speedup vs baseline: 4.6971x; 1.0100x over previous
#include <cuda_runtime.h>
#include <cuda_bf16.h>
#include <math.h>
#include <stdint.h>

#define NN 4096
#define DD 256

// ---------------- scratch (static device globals; no allocation) ----------------
__device__ float          g_h[NN * DD];          // 4 MB : h fp32 (epilogue + logits)
__device__ __nv_bfloat16  g_hb[NN * DD];         // 2 MB : h bf16 [j][d] (B operand)
__device__ __nv_bfloat16  g_Wb[(size_t)NN * NN]; // 32 MB: combined attention weights bf16
__device__ float4 g_wh1[NN];
__device__ float4 g_wh2[NN];
__device__ float  g_pre[NN * DD];                // pre-norm epilogue values
__device__ float  g_rowsq[NN];
__device__ float  g_max[8];

// ---------------- helpers ----------------
__device__ __forceinline__ void atomicMaxF(float* addr, float v) {
    int old = __float_as_int(*addr);
    while (__int_as_float(old) < v) {
        int assumed = old;
        old = atomicCAS((int*)addr, assumed, __float_as_int(v));
        if (old == assumed) break;
    }
}
__device__ __forceinline__ uint32_t smem_u32(const void* p) {
    uint32_t a;
    asm("{ .reg .u64 t; cvta.to.shared.u64 t, %1; cvt.u32.u64 %0, t; }" : "=r"(a) : "l"(p));
    return a;
}
__device__ __forceinline__ void cpasync16(uint32_t dst, const void* src) {
    asm volatile("cp.async.cg.shared.global [%0], [%1], 16;" :: "r"(dst), "l"(src));
}
#define CP_COMMIT()  asm volatile("cp.async.commit_group;" ::: "memory")
#define CP_WAIT(n)   asm volatile("cp.async.wait_group %0;" :: "n"(n) : "memory")
__device__ __forceinline__ void ldmA(uint32_t* r, uint32_t addr) {
    asm volatile("ldmatrix.sync.aligned.m8n8.x4.shared.b16 {%0,%1,%2,%3}, [%4];"
                 : "=r"(r[0]), "=r"(r[1]), "=r"(r[2]), "=r"(r[3]) : "r"(addr));
}
__device__ __forceinline__ void ldmBT(uint32_t* r, uint32_t addr) {
    asm volatile("ldmatrix.sync.aligned.m8n8.x4.trans.shared.b16 {%0,%1,%2,%3}, [%4];"
                 : "=r"(r[0]), "=r"(r[1]), "=r"(r[2]), "=r"(r[3]) : "r"(addr));
}
__device__ __forceinline__ void mma16816(float* c, const uint32_t* a, uint32_t b0, uint32_t b1) {
    asm volatile("mma.sync.aligned.m16n8k16.row.col.f32.bf16.bf16.f32 "
                 "{%0,%1,%2,%3}, {%4,%5,%6,%7}, {%8,%9}, {%0,%1,%2,%3};"
                 : "+f"(c[0]), "+f"(c[1]), "+f"(c[2]), "+f"(c[3])
                 : "r"(a[0]), "r"(a[1]), "r"(a[2]), "r"(a[3]), "r"(b0), "r"(b1));
}

// ---------------- kernel 0: reset maxima + rowsq ----------------
__global__ void k0_init() {
    int idx = blockIdx.x * blockDim.x + threadIdx.x;
    if (idx < NN) g_rowsq[idx] = 0.f;
    if (idx < 8)  g_max[idx] = -3.4e38f;
}

// ---------------- kernel 1: h, h(bf16), Wh1/Wh2, maxima ----------------
__global__ void k1_prep(const float* __restrict__ x, const float* __restrict__ cw,
                        const float* __restrict__ cb, const float* __restrict__ a) {
    int i = blockIdx.x;
    int d = threadIdx.x;
    float v = x[i * DD + d] * cw[0] + cb[0];
    g_h[i * DD + d] = v;
    g_hb[i * DD + d] = __float2bfloat16_rn(v);

    float p[8];
#pragma unroll
    for (int hh = 0; hh < 4; hh++) {
        p[hh]     = v * a[hh * 2 * DD + d];
        p[4 + hh] = v * a[hh * 2 * DD + DD + d];
    }
#pragma unroll
    for (int q = 0; q < 8; q++)
#pragma unroll
        for (int o = 16; o > 0; o >>= 1)
            p[q] += __shfl_xor_sync(0xffffffffu, p[q], o);

    __shared__ float red[8][8];
    int w = d >> 5, lane = d & 31;
    if (lane == 0) {
#pragma unroll
        for (int q = 0; q < 8; q++) red[w][q] = p[q];
    }
    __syncthreads();
    if (d < 8) {
        int q = d;
        float s = 0.f;
#pragma unroll
        for (int ww = 0; ww < 8; ww++) s += red[ww][q];
        if (q < 4) ((float*)g_wh1)[i * 4 + q] = s;
        else       ((float*)g_wh2)[i * 4 + (q - 4)] = s;
        atomicMaxF(&g_max[q], s);
    }
}

// ---------------- kernel 2: W[i,j] = 1/4 sum_h softmax (bf16 out, exp cached) ----------------
__global__ void __launch_bounds__(256) k2_weights(const int* __restrict__ adj) {
    int i   = blockIdx.x;
    int tid = threadIdx.x;
    int lane = tid & 31, w = tid >> 5;
    __shared__ float red[8][4];
    __shared__ float Sinv[4];

    float4 t1 = g_wh1[i];
    float wh1[4] = {t1.x, t1.y, t1.z, t1.w};
    float M[4];
#pragma unroll
    for (int hh = 0; hh < 4; hh++) M[hh] = g_max[hh] + g_max[4 + hh];
    const int* arow = adj + i * NN;

    // pass A: compute all masked exp terms once, cache in registers
    float tc[4][16];
    float sm[4] = {0.f, 0.f, 0.f, 0.f};
#pragma unroll
    for (int it = 0; it < 4; it++) {
        int jb = tid * 4 + it * 1024;
        int4 av = *(const int4*)(arow + jb);
        int aa[4] = {av.x, av.y, av.z, av.w};
#pragma unroll
        for (int u = 0; u < 4; u++) {
            float4 t2 = g_wh2[jb + u];
            float w2[4] = {t2.x, t2.y, t2.z, t2.w};
#pragma unroll
            for (int hh = 0; hh < 4; hh++) {
                float s = wh1[hh] + w2[hh];
                float e = s > 0.f ? s : (__expf(s) - 1.f);
                float t = aa[u] > 0 ? __expf(e - M[hh]) : 0.f;
                tc[hh][it * 4 + u] = t;
                sm[hh] += t;
            }
        }
    }
#pragma unroll
    for (int hh = 0; hh < 4; hh++)
#pragma unroll
        for (int o = 16; o > 0; o >>= 1)
            sm[hh] += __shfl_xor_sync(0xffffffffu, sm[hh], o);
    if (lane == 0) {
        red[w][0] = sm[0]; red[w][1] = sm[1]; red[w][2] = sm[2]; red[w][3] = sm[3];
    }
    __syncthreads();
    if (tid < 4) {
        float s = 0.f;
#pragma unroll
        for (int ww = 0; ww < 8; ww++) s += red[ww][tid];
        Sinv[tid] = 0.25f / s;
    }
    __syncthreads();
    float inv[4] = {Sinv[0], Sinv[1], Sinv[2], Sinv[3]};

    // pass B: combine cached terms, write bf16
#pragma unroll
    for (int it = 0; it < 4; it++) {
        int jb = tid * 4 + it * 1024;
        float res[4];
#pragma unroll
        for (int u = 0; u < 4; u++) {
            int li = it * 4 + u;
            res[u] = tc[0][li] * inv[0] + tc[1][li] * inv[1] +
                     tc[2][li] * inv[2] + tc[3][li] * inv[3];
        }
        __nv_bfloat162 r0 = __floats2bfloat162_rn(res[0], res[1]);
        __nv_bfloat162 r1 = __floats2bfloat162_rn(res[2], res[3]);
        uint2 pk = make_uint2(*(uint32_t*)&r0, *(uint32_t*)&r1);
        *(uint2*)&g_Wb[(size_t)i * NN + jb] = pk;
    }
}

// ---------------- kernel 3: bf16 mma.sync GEMM, cp.async 3-stage, 8 warps ----------------
// BM=64, BN=64, BK=32; 256 threads (8 warps in 2x4). Warp (wr,wc): rows wr*32..+31,
// cols wc*16..+15. grid (64, 4) = 256 CTAs. One __syncthreads per k-tile.
#define BK 32
#define NSTAGE 3
#define A_STRIDE 40   // bf16 elems per row (32 + 8 pad) -> 80B
#define B_STRIDE 72   // bf16 elems per row (64 + 8 pad) -> 144B

__global__ void __launch_bounds__(256) k3_gemm() {
    __shared__ __nv_bfloat16 As[NSTAGE][64][A_STRIDE];
    __shared__ __nv_bfloat16 Bs[NSTAGE][BK][B_STRIDE];
    int tid = threadIdx.x;
    int w = tid >> 5, lane = tid & 31;
    int wr = w >> 2, wc = w & 3;
    int row0 = blockIdx.x * 64;
    int col0 = blockIdx.y * 64;

    float acc[2][2][4];
#pragma unroll
    for (int mt = 0; mt < 2; mt++)
#pragma unroll
        for (int nt = 0; nt < 2; nt++)
#pragma unroll
            for (int q = 0; q < 4; q++) acc[mt][nt][q] = 0.f;

    // A slab: 64 rows x 32 cols = 256 uint4 -> 1 per thread
    int ar = tid >> 2, aq = tid & 3;
    // B slab: 32 rows x 64 cols = 256 uint4 -> 1 per thread
    int br = tid >> 3, bq = tid & 7;

    uint32_t sA[NSTAGE], sB[NSTAGE];
#pragma unroll
    for (int s = 0; s < NSTAGE; s++) {
        sA[s] = smem_u32(&As[s][ar][aq * 8]);
        sB[s] = smem_u32(&Bs[s][br][bq * 8]);
    }

    const int NK = NN / BK;   // 128

#define LOAD_TILE(s, t)                                                        \
    do {                                                                       \
        int k0_ = (t) * BK;                                                    \
        cpasync16(sA[s], &g_Wb[(size_t)(row0 + ar) * NN + k0_ + aq * 8]);      \
        cpasync16(sB[s], &g_hb[(size_t)(k0_ + br) * DD + col0 + bq * 8]);      \
    } while (0)

    LOAD_TILE(0, 0); CP_COMMIT();
    LOAD_TILE(1, 1); CP_COMMIT();

    for (int t = 0; t < NK; t++) {
        CP_WAIT(1);              // tile t's group complete (tile t+1 may be in flight)
        __syncthreads();         // also: all warps done computing tile t-1

        int nxt = t + 2;
        if (nxt < NK) { LOAD_TILE(nxt % NSTAGE, nxt); }
        CP_COMMIT();

        int buf = t % NSTAGE;
#pragma unroll
        for (int ks = 0; ks < 2; ks++) {
            uint32_t a[2][4];
#pragma unroll
            for (int mt = 0; mt < 2; mt++)
                ldmA(a[mt], smem_u32(&As[buf][wr * 32 + mt * 16 + (lane & 15)]
                                            [ks * 16 + (lane >> 4) * 8]));
            uint32_t b[4];
            ldmBT(b, smem_u32(&Bs[buf][ks * 16 + (lane & 15)]
                                      [wc * 16 + (lane >> 4) * 8]));
#pragma unroll
            for (int mt = 0; mt < 2; mt++)
#pragma unroll
                for (int nt = 0; nt < 2; nt++)
                    mma16816(acc[mt][nt], a[mt], b[nt * 2], b[nt * 2 + 1]);
        }
    }
#undef LOAD_TILE

    // epilogue: o = elu(0.5*hpass + 0.5*h); rowsq via quad-reduce + atomic; pre-norm store
#pragma unroll
    for (int mt = 0; mt < 2; mt++) {
        int rT = row0 + wr * 32 + mt * 16 + (lane >> 2);
        int rB = rT + 8;
        float sqT = 0.f, sqB = 0.f;
#pragma unroll
        for (int nt = 0; nt < 2; nt++) {
            int c = col0 + wc * 16 + nt * 8 + (lane & 3) * 2;
            float2 hT = *(const float2*)&g_h[rT * DD + c];
            float2 hB = *(const float2*)&g_h[rB * DD + c];
            float o0 = 0.5f * (acc[mt][nt][0] + hT.x);
            float o1 = 0.5f * (acc[mt][nt][1] + hT.y);
            float o2 = 0.5f * (acc[mt][nt][2] + hB.x);
            float o3 = 0.5f * (acc[mt][nt][3] + hB.y);
            o0 = o0 > 0.f ? o0 : (__expf(o0) - 1.f);
            o1 = o1 > 0.f ? o1 : (__expf(o1) - 1.f);
            o2 = o2 > 0.f ? o2 : (__expf(o2) - 1.f);
            o3 = o3 > 0.f ? o3 : (__expf(o3) - 1.f);
            *(float2*)&g_pre[rT * DD + c] = make_float2(o0, o1);
            *(float2*)&g_pre[rB * DD + c] = make_float2(o2, o3);
            sqT += o0 * o0 + o1 * o1;
            sqB += o2 * o2 + o3 * o3;
        }
        sqT += __shfl_xor_sync(0xffffffffu, sqT, 1);
        sqT += __shfl_xor_sync(0xffffffffu, sqT, 2);
        sqB += __shfl_xor_sync(0xffffffffu, sqB, 1);
        sqB += __shfl_xor_sync(0xffffffffu, sqB, 2);
        if ((lane & 3) == 0) {
            atomicAdd(&g_rowsq[rT], sqT);
            atomicAdd(&g_rowsq[rB], sqB);
        }
    }
}

// ---------------- kernel 4: normalize + bias ----------------
__global__ void __launch_bounds__(256) k4_norm(const float* __restrict__ bias,
                                               float* __restrict__ out) {
    int r = blockIdx.x;
    int c = threadIdx.x;
    float invn = 1.0f / fmaxf(sqrtf(g_rowsq[r]), 1e-12f);
    out[r * DD + c] = g_pre[r * DD + c] * invn + bias[c];
}

// ---------------- launch ----------------
extern "C" void kernel_launch(void* const* d_in, const int* in_sizes, int n_in,
                              void* d_out, int out_size) {
    const float* x    = (const float*)d_in[0];
    const int*   adj  = (const int*)d_in[1];
    const float* cw   = (const float*)d_in[2];
    const float* cb   = (const float*)d_in[3];
    const float* a    = (const float*)d_in[4];
    const float* bias = (const float*)d_in[5];
    float* out = (float*)d_out;

    k0_init<<<16, 256>>>();
    k1_prep<<<NN, 256>>>(x, cw, cb, a);
    k2_weights<<<NN, 256>>>(adj);
    dim3 g3(NN / 64, DD / 64);
    k3_gemm<<<g3, 256>>>();
    k4_norm<<<NN, 256>>>(bias, out);
}

// round 10
// speedup vs baseline: 5.0941x; 1.0845x over previous
#include <cuda_runtime.h>
#include <cuda_bf16.h>
#include <math.h>
#include <stdint.h>

#define NN 4096
#define DD 256

// ---------------- scratch (static device globals; no allocation) ----------------
__device__ float          g_h[NN * DD];          // 4 MB : h fp32
__device__ __nv_bfloat16  g_hb[NN * DD];         // 2 MB : h bf16 [j][d] (B operand)
__device__ __nv_bfloat16  g_Wb[(size_t)NN * NN]; // 32 MB: combined attention weights bf16
__device__ float4 g_wh1[NN];
__device__ float4 g_wh2[NN];
__device__ float4 g_e2[NN];                      // exp(wh2 - m2) per head
__device__ float  g_hp0[NN * DD];                // split-K partial 0
__device__ float  g_hp1[NN * DD];                // split-K partial 1
__device__ float  g_max[8];

// ---------------- helpers ----------------
__device__ __forceinline__ void atomicMaxF(float* addr, float v) {
    int old = __float_as_int(*addr);
    while (__int_as_float(old) < v) {
        int assumed = old;
        old = atomicCAS((int*)addr, assumed, __float_as_int(v));
        if (old == assumed) break;
    }
}
__device__ __forceinline__ uint32_t smem_u32(const void* p) {
    uint32_t a;
    asm("{ .reg .u64 t; cvta.to.shared.u64 t, %1; cvt.u32.u64 %0, t; }" : "=r"(a) : "l"(p));
    return a;
}
__device__ __forceinline__ void cpasync16(uint32_t dst, const void* src) {
    asm volatile("cp.async.cg.shared.global [%0], [%1], 16;" :: "r"(dst), "l"(src));
}
#define CP_COMMIT()  asm volatile("cp.async.commit_group;" ::: "memory")
#define CP_WAIT(n)   asm volatile("cp.async.wait_group %0;" :: "n"(n) : "memory")
__device__ __forceinline__ void ldmA(uint32_t* r, uint32_t addr) {
    asm volatile("ldmatrix.sync.aligned.m8n8.x4.shared.b16 {%0,%1,%2,%3}, [%4];"
                 : "=r"(r[0]), "=r"(r[1]), "=r"(r[2]), "=r"(r[3]) : "r"(addr));
}
__device__ __forceinline__ void ldmBT(uint32_t* r, uint32_t addr) {
    asm volatile("ldmatrix.sync.aligned.m8n8.x4.trans.shared.b16 {%0,%1,%2,%3}, [%4];"
                 : "=r"(r[0]), "=r"(r[1]), "=r"(r[2]), "=r"(r[3]) : "r"(addr));
}
__device__ __forceinline__ void mma16816(float* c, const uint32_t* a, uint32_t b0, uint32_t b1) {
    asm volatile("mma.sync.aligned.m16n8k16.row.col.f32.bf16.bf16.f32 "
                 "{%0,%1,%2,%3}, {%4,%5,%6,%7}, {%8,%9}, {%0,%1,%2,%3};"
                 : "+f"(c[0]), "+f"(c[1]), "+f"(c[2]), "+f"(c[3])
                 : "r"(a[0]), "r"(a[1]), "r"(a[2]), "r"(a[3]), "r"(b0), "r"(b1));
}

// ---------------- kernel 0: reset maxima ----------------
__global__ void k0_init() {
    if (threadIdx.x < 8) g_max[threadIdx.x] = -3.4e38f;
}

// ---------------- kernel 1: h, h(bf16), Wh1/Wh2, maxima ----------------
__global__ void k1_prep(const float* __restrict__ x, const float* __restrict__ cw,
                        const float* __restrict__ cb, const float* __restrict__ a) {
    int i = blockIdx.x;
    int d = threadIdx.x;
    float v = x[i * DD + d] * cw[0] + cb[0];
    g_h[i * DD + d] = v;
    g_hb[i * DD + d] = __float2bfloat16_rn(v);

    float p[8];
#pragma unroll
    for (int hh = 0; hh < 4; hh++) {
        p[hh]     = v * a[hh * 2 * DD + d];
        p[4 + hh] = v * a[hh * 2 * DD + DD + d];
    }
#pragma unroll
    for (int q = 0; q < 8; q++)
#pragma unroll
        for (int o = 16; o > 0; o >>= 1)
            p[q] += __shfl_xor_sync(0xffffffffu, p[q], o);

    __shared__ float red[8][8];
    int w = d >> 5, lane = d & 31;
    if (lane == 0) {
#pragma unroll
        for (int q = 0; q < 8; q++) red[w][q] = p[q];
    }
    __syncthreads();
    if (d < 8) {
        int q = d;
        float s = 0.f;
#pragma unroll
        for (int ww = 0; ww < 8; ww++) s += red[ww][q];
        if (q < 4) ((float*)g_wh1)[i * 4 + q] = s;
        else       ((float*)g_wh2)[i * 4 + (q - 4)] = s;
        atomicMaxF(&g_max[q], s);
    }
}

// ---------------- kernel 1b: E2[j,h] = exp(wh2[j,h] - m2[h]) ----------------
__global__ void __launch_bounds__(256) k1b_e2() {
    int j = blockIdx.x * 256 + threadIdx.x;
    float4 t2 = g_wh2[j];
    float4 e;
    e.x = __expf(t2.x - g_max[4]);
    e.y = __expf(t2.y - g_max[5]);
    e.z = __expf(t2.z - g_max[6]);
    e.w = __expf(t2.w - g_max[7]);
    g_e2[j] = e;
}

// ---------------- kernel 2: W[i,j] = 1/4 sum_h softmax (factorized exp) ----------------
// term T = exp(elu(s)-M), s = wh1+wh2, M = m1+m2:
//   p = E1*E2 = exp(s-M);  s>0 (p>exp(-M)):  T = p
//   s<=0:                 T = exp(exp(s)-1-M) = C*exp(p*exp(M)),  C = exp(-1-M)
__global__ void __launch_bounds__(256) k2_weights(const int* __restrict__ adj) {
    int i   = blockIdx.x;
    int tid = threadIdx.x;
    int lane = tid & 31, w = tid >> 5;
    __shared__ float red[8][4];
    __shared__ float Sinv[4];

    float4 t1 = g_wh1[i];
    float wh1[4] = {t1.x, t1.y, t1.z, t1.w};
    float e1[4], expM[4], Cc[4], pth[4];
#pragma unroll
    for (int hh = 0; hh < 4; hh++) {
        float m1 = g_max[hh], m2 = g_max[4 + hh];
        float M = m1 + m2;
        e1[hh]   = __expf(wh1[hh] - m1);
        expM[hh] = __expf(M);
        Cc[hh]   = __expf(-1.f - M);
        pth[hh]  = __expf(-M);
    }
    const int* arow = adj + i * NN;

    // pass A: compute all masked terms once, cache in registers
    float tc[4][16];
    float sm[4] = {0.f, 0.f, 0.f, 0.f};
#pragma unroll
    for (int it = 0; it < 4; it++) {
        int jb = tid * 4 + it * 1024;
        int4 av = *(const int4*)(arow + jb);
        int aa[4] = {av.x, av.y, av.z, av.w};
#pragma unroll
        for (int u = 0; u < 4; u++) {
            float4 ev = g_e2[jb + u];
            float e2[4] = {ev.x, ev.y, ev.z, ev.w};
#pragma unroll
            for (int hh = 0; hh < 4; hh++) {
                float p  = e1[hh] * e2[hh];
                float tn = Cc[hh] * __expf(p * expM[hh]);   // negative branch
                float t  = p > pth[hh] ? p : tn;
                t = aa[u] > 0 ? t : 0.f;
                tc[hh][it * 4 + u] = t;
                sm[hh] += t;
            }
        }
    }
#pragma unroll
    for (int hh = 0; hh < 4; hh++)
#pragma unroll
        for (int o = 16; o > 0; o >>= 1)
            sm[hh] += __shfl_xor_sync(0xffffffffu, sm[hh], o);
    if (lane == 0) {
        red[w][0] = sm[0]; red[w][1] = sm[1]; red[w][2] = sm[2]; red[w][3] = sm[3];
    }
    __syncthreads();
    if (tid < 4) {
        float s = 0.f;
#pragma unroll
        for (int ww = 0; ww < 8; ww++) s += red[ww][tid];
        Sinv[tid] = 0.25f / s;
    }
    __syncthreads();
    float inv[4] = {Sinv[0], Sinv[1], Sinv[2], Sinv[3]};

    // pass B: combine cached terms, write bf16
#pragma unroll
    for (int it = 0; it < 4; it++) {
        int jb = tid * 4 + it * 1024;
        float res[4];
#pragma unroll
        for (int u = 0; u < 4; u++) {
            int li = it * 4 + u;
            res[u] = tc[0][li] * inv[0] + tc[1][li] * inv[1] +
                     tc[2][li] * inv[2] + tc[3][li] * inv[3];
        }
        __nv_bfloat162 r0 = __floats2bfloat162_rn(res[0], res[1]);
        __nv_bfloat162 r1 = __floats2bfloat162_rn(res[2], res[3]);
        uint2 pk = make_uint2(*(uint32_t*)&r0, *(uint32_t*)&r1);
        *(uint2*)&g_Wb[(size_t)i * NN + jb] = pk;
    }
}

// ---------------- kernel 3: bf16 mma.sync GEMM, cp.async 3-stage, split-K=2 ----------------
// BM=64, BN=64, BK=32; 256 threads (8 warps in 2x4). grid (64, 4, 2) = 512 CTAs.
// Each split-z handles K range [z*2048, (z+1)*2048) and stores raw partials.
#define BK 32
#define NSTAGE 3
#define A_STRIDE 40   // bf16 elems per row (32 + 8 pad) -> 80B
#define B_STRIDE 72   // bf16 elems per row (64 + 8 pad) -> 144B

__global__ void __launch_bounds__(256) k3_gemm() {
    __shared__ __nv_bfloat16 As[NSTAGE][64][A_STRIDE];
    __shared__ __nv_bfloat16 Bs[NSTAGE][BK][B_STRIDE];
    int tid = threadIdx.x;
    int w = tid >> 5, lane = tid & 31;
    int wr = w >> 2, wc = w & 3;
    int row0 = blockIdx.x * 64;
    int col0 = blockIdx.y * 64;
    int kbase = blockIdx.z * (NN / 2);

    float acc[2][2][4];
#pragma unroll
    for (int mt = 0; mt < 2; mt++)
#pragma unroll
        for (int nt = 0; nt < 2; nt++)
#pragma unroll
            for (int q = 0; q < 4; q++) acc[mt][nt][q] = 0.f;

    int ar = tid >> 2, aq = tid & 3;
    int br = tid >> 3, bq = tid & 7;

    uint32_t sA[NSTAGE], sB[NSTAGE];
#pragma unroll
    for (int s = 0; s < NSTAGE; s++) {
        sA[s] = smem_u32(&As[s][ar][aq * 8]);
        sB[s] = smem_u32(&Bs[s][br][bq * 8]);
    }

    const int NKS = (NN / 2) / BK;   // 64

#define LOAD_TILE(s, t)                                                           \
    do {                                                                          \
        int k0_ = kbase + (t) * BK;                                               \
        cpasync16(sA[s], &g_Wb[(size_t)(row0 + ar) * NN + k0_ + aq * 8]);         \
        cpasync16(sB[s], &g_hb[(size_t)(k0_ + br) * DD + col0 + bq * 8]);         \
    } while (0)

    LOAD_TILE(0, 0); CP_COMMIT();
    LOAD_TILE(1, 1); CP_COMMIT();

    for (int t = 0; t < NKS; t++) {
        CP_WAIT(1);
        __syncthreads();

        int nxt = t + 2;
        if (nxt < NKS) { LOAD_TILE(nxt % NSTAGE, nxt); }
        CP_COMMIT();

        int buf = t % NSTAGE;
#pragma unroll
        for (int ks = 0; ks < 2; ks++) {
            uint32_t a[2][4];
#pragma unroll
            for (int mt = 0; mt < 2; mt++)
                ldmA(a[mt], smem_u32(&As[buf][wr * 32 + mt * 16 + (lane & 15)]
                                            [ks * 16 + (lane >> 4) * 8]));
            uint32_t b[4];
            ldmBT(b, smem_u32(&Bs[buf][ks * 16 + (lane & 15)]
                                      [wc * 16 + (lane >> 4) * 8]));
#pragma unroll
            for (int mt = 0; mt < 2; mt++)
#pragma unroll
                for (int nt = 0; nt < 2; nt++)
                    mma16816(acc[mt][nt], a[mt], b[nt * 2], b[nt * 2 + 1]);
        }
    }
#undef LOAD_TILE

    // store raw partials (no epilogue)
    float* dst = blockIdx.z ? g_hp1 : g_hp0;
#pragma unroll
    for (int mt = 0; mt < 2; mt++) {
        int rT = row0 + wr * 32 + mt * 16 + (lane >> 2);
        int rB = rT + 8;
#pragma unroll
        for (int nt = 0; nt < 2; nt++) {
            int c = col0 + wc * 16 + nt * 8 + (lane & 3) * 2;
            *(float2*)&dst[rT * DD + c] = make_float2(acc[mt][nt][0], acc[mt][nt][1]);
            *(float2*)&dst[rB * DD + c] = make_float2(acc[mt][nt][2], acc[mt][nt][3]);
        }
    }
}

// ---------------- kernel 4: epilogue (elu, row L2-norm, bias) ----------------
__global__ void __launch_bounds__(256) k4_norm(const float* __restrict__ bias,
                                               float* __restrict__ out) {
    __shared__ float red[8];
    __shared__ float s_inv;
    int r = blockIdx.x;
    int c = threadIdx.x;
    int lane = c & 31, w = c >> 5;

    float hp = g_hp0[r * DD + c] + g_hp1[r * DD + c];
    float o = 0.5f * (hp + g_h[r * DD + c]);
    o = o > 0.f ? o : (__expf(o) - 1.f);

    float sq = o * o;
#pragma unroll
    for (int off = 16; off > 0; off >>= 1)
        sq += __shfl_xor_sync(0xffffffffu, sq, off);
    if (lane == 0) red[w] = sq;
    __syncthreads();
    if (c < 8) {
        float s = red[c];
#pragma unroll
        for (int off = 4; off > 0; off >>= 1)
            s += __shfl_xor_sync(0xffu, s, off);
        if (c == 0) s_inv = 1.0f / fmaxf(sqrtf(s), 1e-12f);
    }
    __syncthreads();
    out[r * DD + c] = o * s_inv + bias[c];
}

// ---------------- launch ----------------
extern "C" void kernel_launch(void* const* d_in, const int* in_sizes, int n_in,
                              void* d_out, int out_size) {
    const float* x    = (const float*)d_in[0];
    const int*   adj  = (const int*)d_in[1];
    const float* cw   = (const float*)d_in[2];
    const float* cb   = (const float*)d_in[3];
    const float* a    = (const float*)d_in[4];
    const float* bias = (const float*)d_in[5];
    float* out = (float*)d_out;

    k0_init<<<1, 32>>>();
    k1_prep<<<NN, 256>>>(x, cw, cb, a);
    k1b_e2<<<NN / 256, 256>>>();
    k2_weights<<<NN, 256>>>(adj);
    dim3 g3(NN / 64, DD / 64, 2);
    k3_gemm<<<g3, 256>>>();
    k4_norm<<<NN, 256>>>(bias, out);
}